// round 4
// baseline (speedup 1.0000x reference)
#include <cuda_runtime.h>
#include <cuda_bf16.h>
#include <cstdint>

// ---------------------------------------------------------------------------
// LinearMPC: u <- clip(u - 0.01*(u@H^T + f)), 100 iters, B=2048, M=512.
// H symmetric => u@H^T = u@H (row-contiguous reduction).
// R3: H is L2-resident; stream it straight to registers with __ldg (no SMEM
// staging, no cp.async, no per-chunk barriers). u,f live in SMEM [m][b].
// Register double-buffered 8-row H pipeline; 2 block barriers per iteration.
// ---------------------------------------------------------------------------

#define NXD 8
#define NHOR 64
#define MD 512
#define BATCH 2048
#define BT 16            // batch rows per CTA
#define UST 20           // padded row stride for u_s / f_s (floats)
#define NG 8             // H rows per register group
#define NGRP (MD / NG)   // 64
#define ITERS 100
#define STEPC 0.01f
#define THREADS 512

__device__ float g_f[BATCH * MD];

typedef unsigned long long u64;

// ---- packed f32x2 helpers (Blackwell FFMA2) -------------------------------
__device__ __forceinline__ u64 pack2(float lo, float hi) {
    u64 r;
    asm("mov.b64 %0, {%1, %2};" : "=l"(r) : "f"(lo), "f"(hi));
    return r;
}
__device__ __forceinline__ void unpack2(u64 v, float& lo, float& hi) {
    asm("mov.b64 {%0, %1}, %2;" : "=f"(lo), "=f"(hi) : "l"(v));
}
__device__ __forceinline__ void fma2(u64& d, u64 a, u64 b) {
    asm("fma.rn.f32x2 %0, %1, %2, %0;" : "+l"(d) : "l"(a), "l"(b));
}

// ---------------------------------------------------------------------------
// Prologue: f[b, k*8+i] = -2 * Phi[k] @ Q @ (xref[b,k] - xref[b,0])
// ---------------------------------------------------------------------------
__global__ void mpc_f_kernel(const float* __restrict__ xref,
                             const float* __restrict__ Phi,
                             const float* __restrict__ Q) {
    int b = blockIdx.x;
    int k = threadIdx.x;            // 0..63
    const float* xr = xref + (size_t)b * (NHOR + 1) * NXD;

    float dx[NXD];
#pragma unroll
    for (int l = 0; l < NXD; l++)
        dx[l] = xr[k * NXD + l] - xr[l];

    float t[NXD];
#pragma unroll
    for (int j = 0; j < NXD; j++) {
        float s = 0.f;
#pragma unroll
        for (int l = 0; l < NXD; l++)
            s = fmaf(Q[j * NXD + l], dx[l], s);
        t[j] = s;
    }

    const float* Pk = Phi + (size_t)k * NXD * NXD;
#pragma unroll
    for (int i = 0; i < NXD; i++) {
        float s = 0.f;
#pragma unroll
        for (int j = 0; j < NXD; j++)
            s = fmaf(Pk[i * NXD + j], t[j], s);
        g_f[(size_t)b * MD + k * NXD + i] = -2.0f * s;
    }
}

// ---------------------------------------------------------------------------
// Main persistent solver. Thread tile: 2 m x 8 batch (4 f32x2 pairs on b).
// ---------------------------------------------------------------------------
__global__ __launch_bounds__(THREADS, 1)
void mpc_solve_kernel(const float* __restrict__ Hm, float* __restrict__ out) {
    extern __shared__ float sm[];
    float* u_s = sm;                       // [MD][UST]
    float* f_s = sm + MD * UST;            // [MD][UST]

    const int tid    = threadIdx.x;
    const int b_base = blockIdx.x * BT;
    const int m0     = (tid & 255) * 2;    // 2 consecutive m
    const int b0     = (tid >> 8) * 8;     // 8 batch rows (4 pairs)

    // Load f tile into [m][b] layout; zero u.
    for (int i = tid; i < BT * MD; i += THREADS) {
        int b = i >> 9;               // / 512
        int m = i & (MD - 1);
        f_s[m * UST + b] = g_f[(size_t)(b_base + b) * MD + m];
        u_s[m * UST + b] = 0.f;
    }

    u64 u_reg[2][4];
#pragma unroll
    for (int mi = 0; mi < 2; mi++)
#pragma unroll
        for (int bp = 0; bp < 4; bp++)
            u_reg[mi][bp] = 0ull;

    const float2* __restrict__ Hp =
        (const float2*)(Hm + m0);          // row n: Hp[n * (MD/2)]

    __syncthreads();

    for (int it = 0; it < ITERS; it++) {
        // acc = f
        u64 acc[2][4];
#pragma unroll
        for (int mi = 0; mi < 2; mi++) {
            ulonglong2 fa = *(const ulonglong2*)&f_s[(m0 + mi) * UST + b0];
            ulonglong2 fb = *(const ulonglong2*)&f_s[(m0 + mi) * UST + b0 + 4];
            acc[mi][0] = fa.x; acc[mi][1] = fa.y;
            acc[mi][2] = fb.x; acc[mi][3] = fb.y;
        }

        float2 hA[NG], hB[NG];

        // Prime: group 0 -> hA
#pragma unroll
        for (int j = 0; j < NG; j++)
            hA[j] = __ldg(&Hp[(size_t)j * (MD / 2)]);

#define COMPUTE_GROUP(HCUR, HNXT, GIDX)                                       \
        {                                                                     \
            const int gn = ((GIDX) + 1 < NGRP) ? (GIDX) + 1 : (GIDX);         \
            _Pragma("unroll")                                                 \
            for (int j = 0; j < NG; j++)                                      \
                HNXT[j] = __ldg(&Hp[(size_t)(gn * NG + j) * (MD / 2)]);       \
            _Pragma("unroll")                                                 \
            for (int j = 0; j < NG; j++) {                                    \
                const int n = (GIDX) * NG + j;                                \
                ulonglong2 ua = *(const ulonglong2*)&u_s[n * UST + b0];       \
                ulonglong2 ub = *(const ulonglong2*)&u_s[n * UST + b0 + 4];   \
                u64 hh0 = pack2(HCUR[j].x, HCUR[j].x);                        \
                u64 hh1 = pack2(HCUR[j].y, HCUR[j].y);                        \
                fma2(acc[0][0], ua.x, hh0);                                   \
                fma2(acc[0][1], ua.y, hh0);                                   \
                fma2(acc[0][2], ub.x, hh0);                                   \
                fma2(acc[0][3], ub.y, hh0);                                   \
                fma2(acc[1][0], ua.x, hh1);                                   \
                fma2(acc[1][1], ua.y, hh1);                                   \
                fma2(acc[1][2], ub.x, hh1);                                   \
                fma2(acc[1][3], ub.y, hh1);                                   \
            }                                                                 \
        }

#pragma unroll 1
        for (int ng = 0; ng < NGRP; ng += 2) {
            COMPUTE_GROUP(hA, hB, ng);
            COMPUTE_GROUP(hB, hA, ng + 1);
        }
#undef COMPUTE_GROUP

        __syncthreads();   // all warps done reading u_s this iteration

        // u <- clip(u - step*acc); write back to SMEM.
#pragma unroll
        for (int mi = 0; mi < 2; mi++)
#pragma unroll
            for (int bp = 0; bp < 4; bp++) {
                float g0, g1, v0, v1;
                unpack2(acc[mi][bp], g0, g1);
                unpack2(u_reg[mi][bp], v0, v1);
                v0 = fminf(fmaxf(fmaf(-STEPC, g0, v0), -1.0f), 1.0f);
                v1 = fminf(fmaxf(fmaf(-STEPC, g1, v1), -1.0f), 1.0f);
                u64 nv = pack2(v0, v1);
                u_reg[mi][bp] = nv;
                *(u64*)&u_s[(m0 + mi) * UST + b0 + 2 * bp] = nv;
            }

        __syncthreads();   // u_s consistent before next iteration's reads
    }

    // Epilogue: out[b][m], 8 batch x 2 m per thread, coalesced STG.64.
#pragma unroll
    for (int bp = 0; bp < 4; bp++) {
        float v0, v1, w0, w1;
        unpack2(u_reg[0][bp], v0, v1);   // m0   : batches (2bp, 2bp+1)
        unpack2(u_reg[1][bp], w0, w1);   // m0+1 : batches (2bp, 2bp+1)
#pragma unroll
        for (int h = 0; h < 2; h++) {
            int b = b_base + b0 + 2 * bp + h;
            float2 o;
            o.x = h ? v1 : v0;
            o.y = h ? w1 : w0;
            *(float2*)&out[(size_t)b * MD + m0] = o;
        }
    }
}

// ---------------------------------------------------------------------------
extern "C" void kernel_launch(void* const* d_in, const int* in_sizes, int n_in,
                              void* d_out, int out_size) {
    // metadata order: x0, xref, H, Phi, Q
    const float* xref = (const float*)d_in[1];
    const float* H    = (const float*)d_in[2];
    const float* Phi  = (const float*)d_in[3];
    const float* Q    = (const float*)d_in[4];
    float* out        = (float*)d_out;

    const int smem_bytes = (2 * MD * UST) * (int)sizeof(float);   // 80 KB
    cudaFuncSetAttribute(mpc_solve_kernel,
                         cudaFuncAttributeMaxDynamicSharedMemorySize, smem_bytes);

    mpc_f_kernel<<<BATCH, NHOR>>>(xref, Phi, Q);
    mpc_solve_kernel<<<BATCH / BT, THREADS, smem_bytes>>>(H, out);
}